// round 11
// baseline (speedup 1.0000x reference)
#include <cuda_runtime.h>
#include <cuda_bf16.h>
#include <cstdint>
#include <cstddef>

// ============================================================================
// out = (q_lhs @ q_rhs) / (s_lhs * s_rhs), dynamic per-tensor symmetric int8.
// R11: persistent GEMM with dynamic job stealing (atomic counter). 864 full-K
// tile jobs + 320 half-K jobs (tiles 864..1023 split in 2) so the drain tail
// is made of half-duration jobs. s=1 halves -> g_part, merged by add kernel.
// Inner loop identical to validated R8 core (128x128, 256thr, 3-stage).
// ============================================================================

#define MDIM 4096
#define NDIM 4096
#define KDIM 4096

#define FULL_JOBS    864
#define SPLIT_TILES  160                       // tiles [864,1024)
#define N_JOBS       (FULL_JOBS + 2 * SPLIT_TILES)   // 1184
#define GRID_CTAS    304                       // >= 2 CTAs/SM on 152 SMs

// -------------------- device scratch (no allocation allowed) ---------------
__device__ unsigned int g_absmax[2];    // zero-init; reset by last GEMM CTA
__device__ unsigned int g_done;         // finished-CTA ticket
__device__ unsigned int g_next;         // dynamic job counter
__device__ __nv_bfloat16 g_hA[(size_t)MDIM * KDIM];   // lhs quantized bf16, [M,K]
__device__ __nv_bfloat16 g_hB[(size_t)NDIM * KDIM];   // rhs^T quantized bf16, [N,K]
__device__ float g_part[(size_t)SPLIT_TILES * 128 * 128];  // split-K s=1 halves

// -------------------- small helpers -----------------------------------------
__device__ __forceinline__ uint32_t smem_u32(const void* p) {
    uint32_t a;
    asm("{ .reg .u64 t; cvta.to.shared.u64 t, %1; cvt.u32.u64 %0, t; }" : "=r"(a) : "l"(p));
    return a;
}

__device__ __forceinline__ void cp_async16(uint32_t dst, const void* src) {
    asm volatile("cp.async.cg.shared.global [%0], [%1], 16;" :: "r"(dst), "l"(src) : "memory");
}
#define CP_COMMIT() asm volatile("cp.async.commit_group;" ::: "memory")
#define CP_WAIT1()  asm volatile("cp.async.wait_group 1;"  ::: "memory")
#define CP_WAIT0()  asm volatile("cp.async.wait_group 0;"  ::: "memory")

__device__ __forceinline__ void ldmx4(uint32_t& r0, uint32_t& r1, uint32_t& r2, uint32_t& r3,
                                      uint32_t addr) {
    asm volatile("ldmatrix.sync.aligned.m8n8.x4.shared.b16 {%0,%1,%2,%3}, [%4];"
                 : "=r"(r0), "=r"(r1), "=r"(r2), "=r"(r3) : "r"(addr));
}

__device__ __forceinline__ void hmma16816(float* c, const uint32_t* a, const uint32_t* b) {
    asm volatile(
        "mma.sync.aligned.m16n8k16.row.col.f32.bf16.bf16.f32 "
        "{%0,%1,%2,%3}, {%4,%5,%6,%7}, {%8,%9}, {%0,%1,%2,%3};"
        : "+f"(c[0]), "+f"(c[1]), "+f"(c[2]), "+f"(c[3])
        : "r"(a[0]), "r"(a[1]), "r"(a[2]), "r"(a[3]), "r"(b[0]), "r"(b[1]));
}

// ============================================================================
// Kernel 1: fused per-tensor absmax for BOTH tensors, one launch, MLP=2.
// ============================================================================
__global__ void absmax2_kernel(const float4* __restrict__ a,
                               const float4* __restrict__ b, int n4) {
    int half = gridDim.x >> 1;
    int slot = (blockIdx.x >= half) ? 1 : 0;
    const float4* x = slot ? b : a;
    int bid = blockIdx.x - slot * half;
    int stride = half * blockDim.x;

    float m = 0.0f;
    int i = bid * blockDim.x + threadIdx.x;
    for (; i + stride < n4; i += 2 * stride) {
        float4 v0 = x[i];
        float4 v1 = x[i + stride];
        m = fmaxf(m, fmaxf(fmaxf(fabsf(v0.x), fabsf(v0.y)), fmaxf(fabsf(v0.z), fabsf(v0.w))));
        m = fmaxf(m, fmaxf(fmaxf(fabsf(v1.x), fabsf(v1.y)), fmaxf(fabsf(v1.z), fabsf(v1.w))));
    }
    if (i < n4) {
        float4 v = x[i];
        m = fmaxf(m, fmaxf(fmaxf(fabsf(v.x), fabsf(v.y)), fmaxf(fabsf(v.z), fabsf(v.w))));
    }
    #pragma unroll
    for (int o = 16; o; o >>= 1) m = fmaxf(m, __shfl_xor_sync(0xFFFFFFFFu, m, o));
    __shared__ float sm[8];
    if ((threadIdx.x & 31) == 0) sm[threadIdx.x >> 5] = m;
    __syncthreads();
    if (threadIdx.x == 0) {
        float bm = sm[0];
        #pragma unroll
        for (int i2 = 1; i2 < 8; i2++) bm = fmaxf(bm, sm[i2]);
        atomicMax(&g_absmax[slot], __float_as_uint(bm));
    }
}

// ============================================================================
// Kernel 2: quantize lhs -> g_hA (bf16, integer-valued in [-127,127])
// ============================================================================
__device__ __forceinline__ float quantf(float x, float s) {
    return fminf(fmaxf(rintf(x * s), -127.0f), 127.0f);
}

__global__ void quantA_kernel(const float4* __restrict__ lhs) {
    const int n4 = (MDIM * KDIM) / 4;
    float bound = fmaxf(__uint_as_float(g_absmax[0]), 1e-6f);
    float s = 127.0f / bound;
    __nv_bfloat162* h = reinterpret_cast<__nv_bfloat162*>(g_hA);
    for (int i = blockIdx.x * blockDim.x + threadIdx.x; i < n4; i += gridDim.x * blockDim.x) {
        float4 v = lhs[i];
        h[2 * i]     = __floats2bfloat162_rn(quantf(v.x, s), quantf(v.y, s));
        h[2 * i + 1] = __floats2bfloat162_rn(quantf(v.z, s), quantf(v.w, s));
    }
}

// ============================================================================
// Kernel 3: quantize + transpose rhs [K,N] -> g_hB [N,K] (conflict-free reads)
// ============================================================================
__global__ void __launch_bounds__(256) quantBT_kernel(const float* __restrict__ rhs) {
    __shared__ float tile[64][65];
    int n0 = blockIdx.x * 64;
    int k0 = blockIdx.y * 64;
    int tid = threadIdx.x;
    float bound = fmaxf(__uint_as_float(g_absmax[1]), 1e-6f);
    float s = 127.0f / bound;

    {
        int row = tid >> 2;
        int c4  = tid & 3;
        const float4* src = reinterpret_cast<const float4*>(
            rhs + (size_t)(k0 + row) * NDIM + n0);
        #pragma unroll
        for (int i = 0; i < 4; i++) {
            float4 v = src[c4 * 4 + i];
            int c = c4 * 16 + i * 4;
            tile[row][c + 0] = v.x;
            tile[row][c + 1] = v.y;
            tile[row][c + 2] = v.z;
            tile[row][c + 3] = v.w;
        }
    }
    __syncthreads();

    {
        int n  = tid & 63;
        int kc = tid >> 6;
        uint32_t packed[8];
        #pragma unroll
        for (int i = 0; i < 8; i++) {
            __nv_bfloat162 p = __floats2bfloat162_rn(
                quantf(tile[kc * 16 + 2 * i][n], s),
                quantf(tile[kc * 16 + 2 * i + 1][n], s));
            packed[i] = *reinterpret_cast<uint32_t*>(&p);
        }
        __nv_bfloat16* dst = g_hB + (size_t)(n0 + n) * KDIM + k0 + kc * 16;
        uint4* d4 = reinterpret_cast<uint4*>(dst);
        d4[0] = make_uint4(packed[0], packed[1], packed[2], packed[3]);
        d4[1] = make_uint4(packed[4], packed[5], packed[6], packed[7]);
    }
}

// ============================================================================
// Kernel 4: persistent bf16 HMMA GEMM with dynamic job counter.
// Job j < 864: full-K tile j. Job >= 864: half-K of tile 864 + (j-864)/2.
// CTA tile 128x128, K-stage 64, 3-stage cp.async, 2 CTAs/SM.
// ============================================================================
#define TILE_M 128
#define TILE_N 128
#define STAGES 3
#define ST_BYTES 16384
#define SMEM_B_OFF (STAGES * ST_BYTES)
#define SMEM_TOTAL (2 * STAGES * ST_BYTES)

__device__ __forceinline__ uint32_t swz_off(int row, int c16) {
    return (uint32_t)(row * 128 + ((c16 ^ (row & 7)) << 4));
}

__device__ __forceinline__ void load_stage_b(uint32_t sb, int tid, int st,
                                             const char* ga, const char* gb, size_t rstride) {
    uint32_t ab = sb + st * ST_BYTES;
    uint32_t bb = sb + SMEM_B_OFF + st * ST_BYTES;
    #pragma unroll
    for (int i = 0; i < 4; i++) {
        int idx = tid + i * 256;
        int row = idx >> 3, c16 = idx & 7;
        cp_async16(ab + swz_off(row, c16), ga + (size_t)row * rstride + c16 * 16);
    }
    #pragma unroll
    for (int i = 0; i < 4; i++) {
        int idx = tid + i * 256;
        int row = idx >> 3, c16 = idx & 7;
        cp_async16(bb + swz_off(row, c16), gb + (size_t)row * rstride + c16 * 16);
    }
}

struct GemmCtx {
    uint32_t sb;
    int tid;
    const char* gA;
    const char* gB;
    int a_row_l, a_chalf, b_row_l, b_chalf, wm, wn;
};

template <int ST, int NKTL, bool LAST>
__device__ __forceinline__ void k_iter(const GemmCtx& x, int ks, float c[4][4][4]) {
    const size_t rstride = (size_t)KDIM * 2;
    if (LAST) { CP_WAIT0(); } else { CP_WAIT1(); }
    __syncthreads();

    int jn = ks + STAGES - 1;
    if (jn < NKTL) {
        constexpr int ST2 = (ST + 2) % 3;
        load_stage_b(x.sb, x.tid, ST2, x.gA + (size_t)jn * 128, x.gB + (size_t)jn * 128, rstride);
        CP_COMMIT();
    }

    uint32_t ab = x.sb + ST * ST_BYTES;
    uint32_t bb = x.sb + SMEM_B_OFF + ST * ST_BYTES;

    #pragma unroll
    for (int kb = 0; kb < 4; kb++) {
        uint32_t a[4][4];
        uint32_t b[4][2];
        #pragma unroll
        for (int f = 0; f < 4; f++) {
            int row = x.wm * 64 + f * 16 + x.a_row_l;
            ldmx4(a[f][0], a[f][1], a[f][2], a[f][3], ab + swz_off(row, 2 * kb + x.a_chalf));
        }
        #pragma unroll
        for (int p = 0; p < 2; p++) {
            int row = x.wn * 32 + p * 16 + x.b_row_l;
            ldmx4(b[2 * p][0], b[2 * p][1], b[2 * p + 1][0], b[2 * p + 1][1],
                  bb + swz_off(row, 2 * kb + x.b_chalf));
        }
        #pragma unroll
        for (int f = 0; f < 4; f++)
            #pragma unroll
            for (int j = 0; j < 4; j++)
                hmma16816(c[f][j], a[f], b[j]);
    }
}

__global__ void __launch_bounds__(256, 2) qgemm_hmma(float* __restrict__ out) {
    extern __shared__ char smem[];
    __shared__ int s_job;
    GemmCtx x;
    x.sb  = smem_u32(smem);
    x.tid = threadIdx.x;
    int wid  = x.tid >> 5;
    int lane = x.tid & 31;
    x.wm = wid >> 2;
    x.wn = wid & 3;
    x.a_row_l = lane & 15;
    x.a_chalf = lane >> 4;
    x.b_row_l = ((lane >> 4) << 3) + (lane & 7);
    x.b_chalf = (lane >> 3) & 1;

    const size_t rstride = (size_t)KDIM * 2;
    float bl = fmaxf(__uint_as_float(g_absmax[0]), 1e-6f);
    float br = fmaxf(__uint_as_float(g_absmax[1]), 1e-6f);
    float factor = bl * br * (1.0f / (127.0f * 127.0f));
    int g   = lane >> 2;
    int tig = lane & 3;

    for (;;) {
        if (x.tid == 0) s_job = (int)atomicAdd(&g_next, 1u);
        __syncthreads();                       // broadcast + smem reuse safety
        int jid = s_job;
        if (jid >= N_JOBS) break;

        int tile, s;
        bool full;
        if (jid < FULL_JOBS) { tile = jid; s = 0; full = true; }
        else { int h = jid - FULL_JOBS; tile = FULL_JOBS + (h >> 1); s = h & 1; full = false; }
        int n0 = (tile & 31) * TILE_N;
        int m0 = (tile >> 5) * TILE_M;

        size_t kbase = (size_t)s * (KDIM / 2) * 2;
        x.gA = (const char*)g_hA + (size_t)m0 * rstride + kbase;
        x.gB = (const char*)g_hB + (size_t)n0 * rstride + kbase;

        float c[4][4][4];
        #pragma unroll
        for (int f = 0; f < 4; f++)
            #pragma unroll
            for (int j = 0; j < 4; j++)
                #pragma unroll
                for (int q = 0; q < 4; q++) c[f][j][q] = 0.0f;

        #pragma unroll
        for (int j = 0; j < STAGES - 1; j++) {
            load_stage_b(x.sb, x.tid, j, x.gA + (size_t)j * 128, x.gB + (size_t)j * 128, rstride);
            CP_COMMIT();
        }

        if (full) {                    // NKT=64: ks 0..62 in triples, tail 63
            int ks = 0;
            #pragma unroll 1
            for (int t = 0; t < 21; t++) {
                k_iter<0, 64, false>(x, ks + 0, c);
                k_iter<1, 64, false>(x, ks + 1, c);
                k_iter<2, 64, false>(x, ks + 2, c);
                ks += 3;
            }
            k_iter<0, 64, true>(x, 63, c);
        } else {                       // NKT=32: ks 0..29 in triples, 30, 31
            int ks = 0;
            #pragma unroll 1
            for (int t = 0; t < 10; t++) {
                k_iter<0, 32, false>(x, ks + 0, c);
                k_iter<1, 32, false>(x, ks + 1, c);
                k_iter<2, 32, false>(x, ks + 2, c);
                ks += 3;
            }
            k_iter<0, 32, false>(x, 30, c);
            k_iter<1, 32, true>(x, 31, c);
        }

        if (s == 0) {
            #pragma unroll
            for (int f = 0; f < 4; f++) {
                int row0 = m0 + x.wm * 64 + f * 16 + g;
                #pragma unroll
                for (int j = 0; j < 4; j++) {
                    int col = n0 + x.wn * 32 + j * 8 + tig * 2;
                    float2 v0, v1;
                    v0.x = c[f][j][0] * factor;
                    v0.y = c[f][j][1] * factor;
                    v1.x = c[f][j][2] * factor;
                    v1.y = c[f][j][3] * factor;
                    *reinterpret_cast<float2*>(out + (size_t)row0 * NDIM + col)       = v0;
                    *reinterpret_cast<float2*>(out + (size_t)(row0 + 8) * NDIM + col) = v1;
                }
            }
        } else {
            float* pt = g_part + (size_t)(tile - FULL_JOBS) * (128 * 128);
            #pragma unroll
            for (int f = 0; f < 4; f++) {
                int rl = x.wm * 64 + f * 16 + g;
                #pragma unroll
                for (int j = 0; j < 4; j++) {
                    int cl = x.wn * 32 + j * 8 + tig * 2;
                    float2 v0, v1;
                    v0.x = c[f][j][0] * factor;
                    v0.y = c[f][j][1] * factor;
                    v1.x = c[f][j][2] * factor;
                    v1.y = c[f][j][3] * factor;
                    *reinterpret_cast<float2*>(pt + (size_t)rl * 128 + cl)       = v0;
                    *reinterpret_cast<float2*>(pt + (size_t)(rl + 8) * 128 + cl) = v1;
                }
            }
        }
    }

    // Last CTA resets scratch state for the next graph replay.
    if (x.tid == 0) {
        __threadfence();
        unsigned int ticket = atomicInc(&g_done, 0xFFFFFFFFu);
        if (ticket == GRID_CTAS - 1) {
            g_absmax[0] = 0u;
            g_absmax[1] = 0u;
            g_next = 0u;
            g_done = 0u;
            __threadfence();
        }
    }
}

// ============================================================================
// Kernel 5: merge split-K halves: out[tile] += g_part[tile], tiles >= 864.
// ============================================================================
__global__ void __launch_bounds__(256) addpart_kernel(float* __restrict__ out) {
    int t = blockIdx.x;                  // 0..159
    int tile = FULL_JOBS + t;
    int n0 = (tile & 31) * TILE_N;
    int m0 = (tile >> 5) * TILE_M;
    const float4* p = reinterpret_cast<const float4*>(g_part + (size_t)t * (128 * 128));
    for (int i = threadIdx.x; i < 128 * 32; i += 256) {
        int row = i >> 5;
        int c4  = i & 31;
        float4 v = p[i];
        float4* o = reinterpret_cast<float4*>(out + (size_t)(m0 + row) * NDIM + n0 + c4 * 4);
        float4 ov = *o;
        ov.x += v.x; ov.y += v.y; ov.z += v.z; ov.w += v.w;
        *o = ov;
    }
}

// ============================================================================
// Launch
// ============================================================================
extern "C" void kernel_launch(void* const* d_in, const int* in_sizes, int n_in,
                              void* d_out, int out_size) {
    const float* lhs = (const float*)d_in[0];
    const float* rhs = (const float*)d_in[1];
    float* out = (float*)d_out;

    cudaFuncSetAttribute(qgemm_hmma, cudaFuncAttributeMaxDynamicSharedMemorySize, SMEM_TOTAL);

    const int n4 = (MDIM * KDIM) / 4;
    absmax2_kernel<<<1216, 256>>>((const float4*)lhs, (const float4*)rhs, n4);

    quantA_kernel<<<2048, 256>>>((const float4*)lhs);

    dim3 tgrid(NDIM / 64, KDIM / 64);   // (64, 64)
    quantBT_kernel<<<tgrid, 256>>>(rhs);

    qgemm_hmma<<<GRID_CTAS, 256, SMEM_TOTAL>>>(out);
    addpart_kernel<<<SPLIT_TILES, 256>>>(out);
}

// round 12
// speedup vs baseline: 1.3078x; 1.3078x over previous
#include <cuda_runtime.h>
#include <cuda_bf16.h>
#include <cstdint>
#include <cstddef>

// ============================================================================
// out = (q_lhs @ q_rhs) / (s_lhs * s_rhs), dynamic per-tensor symmetric int8.
// R12: GEMM reverted to validated R8 core (128x128, 256thr, 2 CTA/SM, 3-stage,
// static stage offsets; 283.6us / 79.6% tensor). Preprocessing bandwidth work:
// reversed-order second reads (L2 reuse: 64MB tensor fits 126MB L2) + MLP
// unrolling in absmax/quantA.
// ============================================================================

#define MDIM 4096
#define NDIM 4096
#define KDIM 4096

// -------------------- device scratch (no allocation allowed) ---------------
__device__ unsigned int g_absmax[2];    // zero-init; reset by last GEMM CTA
__device__ unsigned int g_done;         // finished-CTA ticket, reset likewise
__device__ __nv_bfloat16 g_hA[(size_t)MDIM * KDIM];   // lhs quantized bf16, [M,K]
__device__ __nv_bfloat16 g_hB[(size_t)NDIM * KDIM];   // rhs^T quantized bf16, [N,K]

// -------------------- small helpers -----------------------------------------
__device__ __forceinline__ uint32_t smem_u32(const void* p) {
    uint32_t a;
    asm("{ .reg .u64 t; cvta.to.shared.u64 t, %1; cvt.u32.u64 %0, t; }" : "=r"(a) : "l"(p));
    return a;
}

__device__ __forceinline__ void cp_async16(uint32_t dst, const void* src) {
    asm volatile("cp.async.cg.shared.global [%0], [%1], 16;" :: "r"(dst), "l"(src) : "memory");
}
#define CP_COMMIT() asm volatile("cp.async.commit_group;" ::: "memory")
#define CP_WAIT1()  asm volatile("cp.async.wait_group 1;"  ::: "memory")
#define CP_WAIT0()  asm volatile("cp.async.wait_group 0;"  ::: "memory")

__device__ __forceinline__ void ldmx4(uint32_t& r0, uint32_t& r1, uint32_t& r2, uint32_t& r3,
                                      uint32_t addr) {
    asm volatile("ldmatrix.sync.aligned.m8n8.x4.shared.b16 {%0,%1,%2,%3}, [%4];"
                 : "=r"(r0), "=r"(r1), "=r"(r2), "=r"(r3) : "r"(addr));
}

__device__ __forceinline__ void hmma16816(float* c, const uint32_t* a, const uint32_t* b) {
    asm volatile(
        "mma.sync.aligned.m16n8k16.row.col.f32.bf16.bf16.f32 "
        "{%0,%1,%2,%3}, {%4,%5,%6,%7}, {%8,%9}, {%0,%1,%2,%3};"
        : "+f"(c[0]), "+f"(c[1]), "+f"(c[2]), "+f"(c[3])
        : "r"(a[0]), "r"(a[1]), "r"(a[2]), "r"(a[3]), "r"(b[0]), "r"(b[1]));
}

__device__ __forceinline__ float max4(float4 v) {
    return fmaxf(fmaxf(fabsf(v.x), fabsf(v.y)), fmaxf(fabsf(v.z), fabsf(v.w)));
}

// ============================================================================
// Kernel 1: fused per-tensor absmax for BOTH tensors, one launch, MLP=4.
// ============================================================================
__global__ void absmax2_kernel(const float4* __restrict__ a,
                               const float4* __restrict__ b, int n4) {
    int half = gridDim.x >> 1;
    int slot = (blockIdx.x >= half) ? 1 : 0;
    const float4* x = slot ? b : a;
    int bid = blockIdx.x - slot * half;
    int stride = half * blockDim.x;

    float m = 0.0f;
    int i = bid * blockDim.x + threadIdx.x;
    for (; i + 3 * stride < n4; i += 4 * stride) {
        float4 v0 = x[i];
        float4 v1 = x[i + stride];
        float4 v2 = x[i + 2 * stride];
        float4 v3 = x[i + 3 * stride];
        m = fmaxf(m, fmaxf(fmaxf(max4(v0), max4(v1)), fmaxf(max4(v2), max4(v3))));
    }
    for (; i < n4; i += stride) m = fmaxf(m, max4(x[i]));

    #pragma unroll
    for (int o = 16; o; o >>= 1) m = fmaxf(m, __shfl_xor_sync(0xFFFFFFFFu, m, o));
    __shared__ float sm[8];
    if ((threadIdx.x & 31) == 0) sm[threadIdx.x >> 5] = m;
    __syncthreads();
    if (threadIdx.x == 0) {
        float bm = sm[0];
        #pragma unroll
        for (int i2 = 1; i2 < 8; i2++) bm = fmaxf(bm, sm[i2]);
        atomicMax(&g_absmax[slot], __float_as_uint(bm));
    }
}

// ============================================================================
// Kernel 2: quantize lhs -> g_hA. REVERSED traversal: the tail of lhs is
// still L2-resident from the absmax scan (64MB tensor, 126MB L2). MLP=2.
// ============================================================================
__device__ __forceinline__ float quantf(float x, float s) {
    return fminf(fmaxf(rintf(x * s), -127.0f), 127.0f);
}

__global__ void quantA_kernel(const float4* __restrict__ lhs) {
    const int n4 = (MDIM * KDIM) / 4;                 // 4194304
    const int stride = gridDim.x * blockDim.x;        // 524288 -> 8 items/thread
    float bound = fmaxf(__uint_as_float(g_absmax[0]), 1e-6f);
    float s = 127.0f / bound;
    __nv_bfloat162* h = reinterpret_cast<__nv_bfloat162*>(g_hA);

    int i = n4 - 1 - (int)(blockIdx.x * blockDim.x + threadIdx.x);
    for (; i - stride >= 0; i -= 2 * stride) {
        float4 v0 = lhs[i];
        float4 v1 = lhs[i - stride];
        h[2 * i]                  = __floats2bfloat162_rn(quantf(v0.x, s), quantf(v0.y, s));
        h[2 * i + 1]              = __floats2bfloat162_rn(quantf(v0.z, s), quantf(v0.w, s));
        h[2 * (i - stride)]       = __floats2bfloat162_rn(quantf(v1.x, s), quantf(v1.y, s));
        h[2 * (i - stride) + 1]   = __floats2bfloat162_rn(quantf(v1.z, s), quantf(v1.w, s));
    }
    if (i >= 0) {
        float4 v = lhs[i];
        h[2 * i]     = __floats2bfloat162_rn(quantf(v.x, s), quantf(v.y, s));
        h[2 * i + 1] = __floats2bfloat162_rn(quantf(v.z, s), quantf(v.w, s));
    }
}

// ============================================================================
// Kernel 3: quantize + transpose rhs [K,N] -> g_hB [N,K]. Reversed block
// mapping for L2 reuse of the absmax scan tail. Conflict-free smem phases.
// ============================================================================
__global__ void __launch_bounds__(256) quantBT_kernel(const float* __restrict__ rhs) {
    __shared__ float tile[64][65];
    int bx = gridDim.x - 1 - blockIdx.x;
    int by = gridDim.y - 1 - blockIdx.y;
    int n0 = bx * 64;
    int k0 = by * 64;
    int tid = threadIdx.x;
    float bound = fmaxf(__uint_as_float(g_absmax[1]), 1e-6f);
    float s = 127.0f / bound;

    {
        int row = tid >> 2;
        int c4  = tid & 3;
        const float4* src = reinterpret_cast<const float4*>(
            rhs + (size_t)(k0 + row) * NDIM + n0);
        #pragma unroll
        for (int i = 0; i < 4; i++) {
            float4 v = src[c4 * 4 + i];
            int c = c4 * 16 + i * 4;
            tile[row][c + 0] = v.x;
            tile[row][c + 1] = v.y;
            tile[row][c + 2] = v.z;
            tile[row][c + 3] = v.w;
        }
    }
    __syncthreads();

    {
        int n  = tid & 63;
        int kc = tid >> 6;
        uint32_t packed[8];
        #pragma unroll
        for (int i = 0; i < 8; i++) {
            __nv_bfloat162 p = __floats2bfloat162_rn(
                quantf(tile[kc * 16 + 2 * i][n], s),
                quantf(tile[kc * 16 + 2 * i + 1][n], s));
            packed[i] = *reinterpret_cast<uint32_t*>(&p);
        }
        __nv_bfloat16* dst = g_hB + (size_t)(n0 + n) * KDIM + k0 + kc * 16;
        uint4* d4 = reinterpret_cast<uint4*>(dst);
        d4[0] = make_uint4(packed[0], packed[1], packed[2], packed[3]);
        d4[1] = make_uint4(packed[4], packed[5], packed[6], packed[7]);
    }
}

// ============================================================================
// Kernel 4: bf16 HMMA GEMM (R8 core, validated). CTA tile 128x128, K-stage 64,
// 3-stage cp.async pipe, 2 CTAs/SM, static stage offsets via unroll-by-3.
// ============================================================================
#define TILE_M 128
#define TILE_N 128
#define STAGES 3
#define ST_BYTES 16384
#define SMEM_B_OFF (STAGES * ST_BYTES)
#define SMEM_TOTAL (2 * STAGES * ST_BYTES)
#define NKT (KDIM / 64)                 // 64

__device__ __forceinline__ uint32_t swz_off(int row, int c16) {
    return (uint32_t)(row * 128 + ((c16 ^ (row & 7)) << 4));
}

__device__ __forceinline__ void load_stage_b(uint32_t sb, int tid, int st,
                                             const char* ga, const char* gb, size_t rstride) {
    uint32_t ab = sb + st * ST_BYTES;
    uint32_t bb = sb + SMEM_B_OFF + st * ST_BYTES;
    #pragma unroll
    for (int i = 0; i < 4; i++) {
        int idx = tid + i * 256;
        int row = idx >> 3, c16 = idx & 7;
        cp_async16(ab + swz_off(row, c16), ga + (size_t)row * rstride + c16 * 16);
    }
    #pragma unroll
    for (int i = 0; i < 4; i++) {
        int idx = tid + i * 256;
        int row = idx >> 3, c16 = idx & 7;
        cp_async16(bb + swz_off(row, c16), gb + (size_t)row * rstride + c16 * 16);
    }
}

struct GemmCtx {
    uint32_t sb;
    int tid;
    const char* gA;
    const char* gB;
    int a_row_l, a_chalf, b_row_l, b_chalf, wm, wn;
};

template <int ST, bool LAST>
__device__ __forceinline__ void k_iter(const GemmCtx& x, int ks, float c[4][4][4]) {
    const size_t rstride = (size_t)KDIM * 2;
    if (LAST) { CP_WAIT0(); } else { CP_WAIT1(); }
    __syncthreads();

    int jn = ks + STAGES - 1;
    if (jn < NKT) {
        constexpr int ST2 = (ST + 2) % 3;
        load_stage_b(x.sb, x.tid, ST2, x.gA + (size_t)jn * 128, x.gB + (size_t)jn * 128, rstride);
        CP_COMMIT();
    }

    uint32_t ab = x.sb + ST * ST_BYTES;
    uint32_t bb = x.sb + SMEM_B_OFF + ST * ST_BYTES;

    #pragma unroll
    for (int kb = 0; kb < 4; kb++) {
        uint32_t a[4][4];
        uint32_t b[4][2];
        #pragma unroll
        for (int f = 0; f < 4; f++) {
            int row = x.wm * 64 + f * 16 + x.a_row_l;
            ldmx4(a[f][0], a[f][1], a[f][2], a[f][3], ab + swz_off(row, 2 * kb + x.a_chalf));
        }
        #pragma unroll
        for (int p = 0; p < 2; p++) {
            int row = x.wn * 32 + p * 16 + x.b_row_l;
            ldmx4(b[2 * p][0], b[2 * p][1], b[2 * p + 1][0], b[2 * p + 1][1],
                  bb + swz_off(row, 2 * kb + x.b_chalf));
        }
        #pragma unroll
        for (int f = 0; f < 4; f++)
            #pragma unroll
            for (int j = 0; j < 4; j++)
                hmma16816(c[f][j], a[f], b[j]);
    }
}

__global__ void __launch_bounds__(256, 2) qgemm_hmma(float* __restrict__ out) {
    extern __shared__ char smem[];
    GemmCtx x;
    x.sb  = smem_u32(smem);
    x.tid = threadIdx.x;
    int wid  = x.tid >> 5;
    int lane = x.tid & 31;
    x.wm = wid >> 2;
    x.wn = wid & 3;
    int m0 = blockIdx.y * TILE_M;
    int n0 = blockIdx.x * TILE_N;

    x.gA = (const char*)g_hA + (size_t)m0 * KDIM * 2;
    x.gB = (const char*)g_hB + (size_t)n0 * KDIM * 2;
    const size_t rstride = (size_t)KDIM * 2;

    float c[4][4][4];
    #pragma unroll
    for (int f = 0; f < 4; f++)
        #pragma unroll
        for (int j = 0; j < 4; j++)
            #pragma unroll
            for (int q = 0; q < 4; q++) c[f][j][q] = 0.0f;

    x.a_row_l = lane & 15;
    x.a_chalf = lane >> 4;
    x.b_row_l = ((lane >> 4) << 3) + (lane & 7);
    x.b_chalf = (lane >> 3) & 1;

    #pragma unroll
    for (int j = 0; j < STAGES - 1; j++) {
        load_stage_b(x.sb, x.tid, j, x.gA + (size_t)j * 128, x.gB + (size_t)j * 128, rstride);
        CP_COMMIT();
    }

    int ks = 0;
    #pragma unroll 1
    for (int t = 0; t < 21; t++) {
        k_iter<0, false>(x, ks + 0, c);
        k_iter<1, false>(x, ks + 1, c);
        k_iter<2, false>(x, ks + 2, c);
        ks += 3;
    }
    k_iter<0, true>(x, 63, c);

    float bl = fmaxf(__uint_as_float(g_absmax[0]), 1e-6f);
    float br = fmaxf(__uint_as_float(g_absmax[1]), 1e-6f);
    float factor = bl * br * (1.0f / (127.0f * 127.0f));

    int g   = lane >> 2;
    int tig = lane & 3;
    #pragma unroll
    for (int f = 0; f < 4; f++) {
        int row0 = m0 + x.wm * 64 + f * 16 + g;
        #pragma unroll
        for (int j = 0; j < 4; j++) {
            int col = n0 + x.wn * 32 + j * 8 + tig * 2;
            float2 v0, v1;
            v0.x = c[f][j][0] * factor;
            v0.y = c[f][j][1] * factor;
            v1.x = c[f][j][2] * factor;
            v1.y = c[f][j][3] * factor;
            *reinterpret_cast<float2*>(out + (size_t)row0 * NDIM + col)       = v0;
            *reinterpret_cast<float2*>(out + (size_t)(row0 + 8) * NDIM + col) = v1;
        }
    }

    // Last CTA resets scratch state for the next graph replay.
    __syncthreads();
    if (x.tid == 0) {
        __threadfence();
        unsigned int ticket = atomicInc(&g_done, 0xFFFFFFFFu);
        if (ticket == gridDim.x * gridDim.y - 1) {
            g_absmax[0] = 0u;
            g_absmax[1] = 0u;
            g_done = 0u;
            __threadfence();
        }
    }
}

// ============================================================================
// Launch
// ============================================================================
extern "C" void kernel_launch(void* const* d_in, const int* in_sizes, int n_in,
                              void* d_out, int out_size) {
    const float* lhs = (const float*)d_in[0];
    const float* rhs = (const float*)d_in[1];
    float* out = (float*)d_out;

    cudaFuncSetAttribute(qgemm_hmma, cudaFuncAttributeMaxDynamicSharedMemorySize, SMEM_TOTAL);

    const int n4 = (MDIM * KDIM) / 4;
    absmax2_kernel<<<1216, 256>>>((const float4*)lhs, (const float4*)rhs, n4);

    quantA_kernel<<<2048, 256>>>((const float4*)lhs);

    dim3 tgrid(NDIM / 64, KDIM / 64);   // (64, 64)
    quantBT_kernel<<<tgrid, 256>>>(rhs);

    dim3 ggrid(NDIM / TILE_N, MDIM / TILE_M);   // (32, 32)
    qgemm_hmma<<<ggrid, 256, SMEM_TOTAL>>>(out);
}

// round 13
// speedup vs baseline: 1.3219x; 1.0108x over previous
#include <cuda_runtime.h>
#include <cuda_bf16.h>
#include <cstdint>
#include <cstddef>

// ============================================================================
// out = (q_lhs @ q_rhs) / (s_lhs * s_rhs), dynamic per-tensor symmetric int8.
// R13: GEMM = validated R8 core (untouched, 285us / 79.6% tensor).
// Pre-processing: quantA rewritten for 16B stores (8 floats/thread),
// quantA+quantBT merged into ONE launch (concurrent bandwidth phases),
// reversed traversal kept for L2 reuse after absmax.
// ============================================================================

#define MDIM 4096
#define NDIM 4096
#define KDIM 4096

#define QA_BLOCKS 2048
#define QBT_BLOCKS (64 * 64)                 // 4096 tiles of 64x64
#define QAB_GRID  (QA_BLOCKS + QBT_BLOCKS)   // 6144

// -------------------- device scratch (no allocation allowed) ---------------
__device__ unsigned int g_absmax[2];    // zero-init; reset by last GEMM CTA
__device__ unsigned int g_done;         // finished-CTA ticket, reset likewise
__device__ __nv_bfloat16 g_hA[(size_t)MDIM * KDIM];   // lhs quantized bf16, [M,K]
__device__ __nv_bfloat16 g_hB[(size_t)NDIM * KDIM];   // rhs^T quantized bf16, [N,K]

// -------------------- small helpers -----------------------------------------
__device__ __forceinline__ uint32_t smem_u32(const void* p) {
    uint32_t a;
    asm("{ .reg .u64 t; cvta.to.shared.u64 t, %1; cvt.u32.u64 %0, t; }" : "=r"(a) : "l"(p));
    return a;
}

__device__ __forceinline__ void cp_async16(uint32_t dst, const void* src) {
    asm volatile("cp.async.cg.shared.global [%0], [%1], 16;" :: "r"(dst), "l"(src) : "memory");
}
#define CP_COMMIT() asm volatile("cp.async.commit_group;" ::: "memory")
#define CP_WAIT1()  asm volatile("cp.async.wait_group 1;"  ::: "memory")
#define CP_WAIT0()  asm volatile("cp.async.wait_group 0;"  ::: "memory")

__device__ __forceinline__ void ldmx4(uint32_t& r0, uint32_t& r1, uint32_t& r2, uint32_t& r3,
                                      uint32_t addr) {
    asm volatile("ldmatrix.sync.aligned.m8n8.x4.shared.b16 {%0,%1,%2,%3}, [%4];"
                 : "=r"(r0), "=r"(r1), "=r"(r2), "=r"(r3) : "r"(addr));
}

__device__ __forceinline__ void hmma16816(float* c, const uint32_t* a, const uint32_t* b) {
    asm volatile(
        "mma.sync.aligned.m16n8k16.row.col.f32.bf16.bf16.f32 "
        "{%0,%1,%2,%3}, {%4,%5,%6,%7}, {%8,%9}, {%0,%1,%2,%3};"
        : "+f"(c[0]), "+f"(c[1]), "+f"(c[2]), "+f"(c[3])
        : "r"(a[0]), "r"(a[1]), "r"(a[2]), "r"(a[3]), "r"(b[0]), "r"(b[1]));
}

__device__ __forceinline__ float max4(float4 v) {
    return fmaxf(fmaxf(fabsf(v.x), fabsf(v.y)), fmaxf(fabsf(v.z), fabsf(v.w)));
}

__device__ __forceinline__ float quantf(float x, float s) {
    return fminf(fmaxf(rintf(x * s), -127.0f), 127.0f);
}

// ============================================================================
// Kernel 1: fused per-tensor absmax for BOTH tensors, one launch, MLP=4.
// ============================================================================
__global__ void absmax2_kernel(const float4* __restrict__ a,
                               const float4* __restrict__ b, int n4) {
    int half = gridDim.x >> 1;
    int slot = (blockIdx.x >= half) ? 1 : 0;
    const float4* x = slot ? b : a;
    int bid = blockIdx.x - slot * half;
    int stride = half * blockDim.x;

    float m = 0.0f;
    int i = bid * blockDim.x + threadIdx.x;
    for (; i + 3 * stride < n4; i += 4 * stride) {
        float4 v0 = x[i];
        float4 v1 = x[i + stride];
        float4 v2 = x[i + 2 * stride];
        float4 v3 = x[i + 3 * stride];
        m = fmaxf(m, fmaxf(fmaxf(max4(v0), max4(v1)), fmaxf(max4(v2), max4(v3))));
    }
    for (; i < n4; i += stride) m = fmaxf(m, max4(x[i]));

    #pragma unroll
    for (int o = 16; o; o >>= 1) m = fmaxf(m, __shfl_xor_sync(0xFFFFFFFFu, m, o));
    __shared__ float sm[8];
    if ((threadIdx.x & 31) == 0) sm[threadIdx.x >> 5] = m;
    __syncthreads();
    if (threadIdx.x == 0) {
        float bm = sm[0];
        #pragma unroll
        for (int i2 = 1; i2 < 8; i2++) bm = fmaxf(bm, sm[i2]);
        atomicMax(&g_absmax[slot], __float_as_uint(bm));
    }
}

// ============================================================================
// Kernel 2 (merged): quantA + quantBT in one launch.
// Blocks [0, QA_BLOCKS): lhs -> g_hA. 8 floats/thread, single 16B store,
// reversed traversal (L2 reuse of absmax tail).
// Blocks [QA_BLOCKS, QAB_GRID): rhs 64x64 tile transpose -> g_hB,
// reversed tile mapping, conflict-free smem phases, 2x16B stores.
// ============================================================================
__global__ void __launch_bounds__(256) quantAB_kernel(const float* __restrict__ lhs,
                                                      const float* __restrict__ rhs) {
    if (blockIdx.x < QA_BLOCKS) {
        // ---------------- quantA: units of 8 floats (32B in, 16B out) -------
        const int n8 = (MDIM * KDIM) / 8;                 // 2097152
        const int stride = QA_BLOCKS * 256;               // 524288 -> 4 units/thread
        float bound = fmaxf(__uint_as_float(g_absmax[0]), 1e-6f);
        float s = 127.0f / bound;
        const float4* in = reinterpret_cast<const float4*>(lhs);
        uint4* outv = reinterpret_cast<uint4*>(g_hA);

        int i = n8 - 1 - (int)(blockIdx.x * 256 + threadIdx.x);
        for (; i - stride >= 0; i -= 2 * stride) {
            float4 a0 = in[2 * i];
            float4 a1 = in[2 * i + 1];
            float4 b0 = in[2 * (i - stride)];
            float4 b1 = in[2 * (i - stride) + 1];
            uint4 pa, pb;
            __nv_bfloat162 t;
            t = __floats2bfloat162_rn(quantf(a0.x, s), quantf(a0.y, s)); pa.x = *(uint32_t*)&t;
            t = __floats2bfloat162_rn(quantf(a0.z, s), quantf(a0.w, s)); pa.y = *(uint32_t*)&t;
            t = __floats2bfloat162_rn(quantf(a1.x, s), quantf(a1.y, s)); pa.z = *(uint32_t*)&t;
            t = __floats2bfloat162_rn(quantf(a1.z, s), quantf(a1.w, s)); pa.w = *(uint32_t*)&t;
            t = __floats2bfloat162_rn(quantf(b0.x, s), quantf(b0.y, s)); pb.x = *(uint32_t*)&t;
            t = __floats2bfloat162_rn(quantf(b0.z, s), quantf(b0.w, s)); pb.y = *(uint32_t*)&t;
            t = __floats2bfloat162_rn(quantf(b1.x, s), quantf(b1.y, s)); pb.z = *(uint32_t*)&t;
            t = __floats2bfloat162_rn(quantf(b1.z, s), quantf(b1.w, s)); pb.w = *(uint32_t*)&t;
            outv[i] = pa;
            outv[i - stride] = pb;
        }
        if (i >= 0) {
            float4 a0 = in[2 * i];
            float4 a1 = in[2 * i + 1];
            uint4 pa;
            __nv_bfloat162 t;
            t = __floats2bfloat162_rn(quantf(a0.x, s), quantf(a0.y, s)); pa.x = *(uint32_t*)&t;
            t = __floats2bfloat162_rn(quantf(a0.z, s), quantf(a0.w, s)); pa.y = *(uint32_t*)&t;
            t = __floats2bfloat162_rn(quantf(a1.x, s), quantf(a1.y, s)); pa.z = *(uint32_t*)&t;
            t = __floats2bfloat162_rn(quantf(a1.z, s), quantf(a1.w, s)); pa.w = *(uint32_t*)&t;
            outv[i] = pa;
        }
    } else {
        // ---------------- quantBT: 64x64 tile, transpose + quantize ---------
        __shared__ float tile[64][65];
        int t64 = (int)blockIdx.x - QA_BLOCKS;            // 0..4095
        int bx = 63 - (t64 & 63);                         // reversed mapping
        int by = 63 - (t64 >> 6);
        int n0 = bx * 64;
        int k0 = by * 64;
        int tid = threadIdx.x;
        float bound = fmaxf(__uint_as_float(g_absmax[1]), 1e-6f);
        float s = 127.0f / bound;

        {
            int row = tid >> 2;
            int c4  = tid & 3;
            const float4* src = reinterpret_cast<const float4*>(
                rhs + (size_t)(k0 + row) * NDIM + n0);
            #pragma unroll
            for (int i = 0; i < 4; i++) {
                float4 v = src[c4 * 4 + i];
                int c = c4 * 16 + i * 4;
                tile[row][c + 0] = v.x;
                tile[row][c + 1] = v.y;
                tile[row][c + 2] = v.z;
                tile[row][c + 3] = v.w;
            }
        }
        __syncthreads();

        {
            int n  = tid & 63;
            int kc = tid >> 6;
            uint32_t packed[8];
            #pragma unroll
            for (int i = 0; i < 8; i++) {
                __nv_bfloat162 p = __floats2bfloat162_rn(
                    quantf(tile[kc * 16 + 2 * i][n], s),
                    quantf(tile[kc * 16 + 2 * i + 1][n], s));
                packed[i] = *reinterpret_cast<uint32_t*>(&p);
            }
            __nv_bfloat16* dst = g_hB + (size_t)(n0 + n) * KDIM + k0 + kc * 16;
            uint4* d4 = reinterpret_cast<uint4*>(dst);
            d4[0] = make_uint4(packed[0], packed[1], packed[2], packed[3]);
            d4[1] = make_uint4(packed[4], packed[5], packed[6], packed[7]);
        }
    }
}

// ============================================================================
// Kernel 3: bf16 HMMA GEMM (R8 core, validated). CTA tile 128x128, K-stage 64,
// 3-stage cp.async pipe, 2 CTAs/SM, static stage offsets via unroll-by-3.
// ============================================================================
#define TILE_M 128
#define TILE_N 128
#define STAGES 3
#define ST_BYTES 16384
#define SMEM_B_OFF (STAGES * ST_BYTES)
#define SMEM_TOTAL (2 * STAGES * ST_BYTES)
#define NKT (KDIM / 64)                 // 64

__device__ __forceinline__ uint32_t swz_off(int row, int c16) {
    return (uint32_t)(row * 128 + ((c16 ^ (row & 7)) << 4));
}

__device__ __forceinline__ void load_stage_b(uint32_t sb, int tid, int st,
                                             const char* ga, const char* gb, size_t rstride) {
    uint32_t ab = sb + st * ST_BYTES;
    uint32_t bb = sb + SMEM_B_OFF + st * ST_BYTES;
    #pragma unroll
    for (int i = 0; i < 4; i++) {
        int idx = tid + i * 256;
        int row = idx >> 3, c16 = idx & 7;
        cp_async16(ab + swz_off(row, c16), ga + (size_t)row * rstride + c16 * 16);
    }
    #pragma unroll
    for (int i = 0; i < 4; i++) {
        int idx = tid + i * 256;
        int row = idx >> 3, c16 = idx & 7;
        cp_async16(bb + swz_off(row, c16), gb + (size_t)row * rstride + c16 * 16);
    }
}

struct GemmCtx {
    uint32_t sb;
    int tid;
    const char* gA;
    const char* gB;
    int a_row_l, a_chalf, b_row_l, b_chalf, wm, wn;
};

template <int ST, bool LAST>
__device__ __forceinline__ void k_iter(const GemmCtx& x, int ks, float c[4][4][4]) {
    const size_t rstride = (size_t)KDIM * 2;
    if (LAST) { CP_WAIT0(); } else { CP_WAIT1(); }
    __syncthreads();

    int jn = ks + STAGES - 1;
    if (jn < NKT) {
        constexpr int ST2 = (ST + 2) % 3;
        load_stage_b(x.sb, x.tid, ST2, x.gA + (size_t)jn * 128, x.gB + (size_t)jn * 128, rstride);
        CP_COMMIT();
    }

    uint32_t ab = x.sb + ST * ST_BYTES;
    uint32_t bb = x.sb + SMEM_B_OFF + ST * ST_BYTES;

    #pragma unroll
    for (int kb = 0; kb < 4; kb++) {
        uint32_t a[4][4];
        uint32_t b[4][2];
        #pragma unroll
        for (int f = 0; f < 4; f++) {
            int row = x.wm * 64 + f * 16 + x.a_row_l;
            ldmx4(a[f][0], a[f][1], a[f][2], a[f][3], ab + swz_off(row, 2 * kb + x.a_chalf));
        }
        #pragma unroll
        for (int p = 0; p < 2; p++) {
            int row = x.wn * 32 + p * 16 + x.b_row_l;
            ldmx4(b[2 * p][0], b[2 * p][1], b[2 * p + 1][0], b[2 * p + 1][1],
                  bb + swz_off(row, 2 * kb + x.b_chalf));
        }
        #pragma unroll
        for (int f = 0; f < 4; f++)
            #pragma unroll
            for (int j = 0; j < 4; j++)
                hmma16816(c[f][j], a[f], b[j]);
    }
}

__global__ void __launch_bounds__(256, 2) qgemm_hmma(float* __restrict__ out) {
    extern __shared__ char smem[];
    GemmCtx x;
    x.sb  = smem_u32(smem);
    x.tid = threadIdx.x;
    int wid  = x.tid >> 5;
    int lane = x.tid & 31;
    x.wm = wid >> 2;
    x.wn = wid & 3;
    int m0 = blockIdx.y * TILE_M;
    int n0 = blockIdx.x * TILE_N;

    x.gA = (const char*)g_hA + (size_t)m0 * KDIM * 2;
    x.gB = (const char*)g_hB + (size_t)n0 * KDIM * 2;
    const size_t rstride = (size_t)KDIM * 2;

    float c[4][4][4];
    #pragma unroll
    for (int f = 0; f < 4; f++)
        #pragma unroll
        for (int j = 0; j < 4; j++)
            #pragma unroll
            for (int q = 0; q < 4; q++) c[f][j][q] = 0.0f;

    x.a_row_l = lane & 15;
    x.a_chalf = lane >> 4;
    x.b_row_l = ((lane >> 4) << 3) + (lane & 7);
    x.b_chalf = (lane >> 3) & 1;

    #pragma unroll
    for (int j = 0; j < STAGES - 1; j++) {
        load_stage_b(x.sb, x.tid, j, x.gA + (size_t)j * 128, x.gB + (size_t)j * 128, rstride);
        CP_COMMIT();
    }

    int ks = 0;
    #pragma unroll 1
    for (int t = 0; t < 21; t++) {
        k_iter<0, false>(x, ks + 0, c);
        k_iter<1, false>(x, ks + 1, c);
        k_iter<2, false>(x, ks + 2, c);
        ks += 3;
    }
    k_iter<0, true>(x, 63, c);

    float bl = fmaxf(__uint_as_float(g_absmax[0]), 1e-6f);
    float br = fmaxf(__uint_as_float(g_absmax[1]), 1e-6f);
    float factor = bl * br * (1.0f / (127.0f * 127.0f));

    int g   = lane >> 2;
    int tig = lane & 3;
    #pragma unroll
    for (int f = 0; f < 4; f++) {
        int row0 = m0 + x.wm * 64 + f * 16 + g;
        #pragma unroll
        for (int j = 0; j < 4; j++) {
            int col = n0 + x.wn * 32 + j * 8 + tig * 2;
            float2 v0, v1;
            v0.x = c[f][j][0] * factor;
            v0.y = c[f][j][1] * factor;
            v1.x = c[f][j][2] * factor;
            v1.y = c[f][j][3] * factor;
            *reinterpret_cast<float2*>(out + (size_t)row0 * NDIM + col)       = v0;
            *reinterpret_cast<float2*>(out + (size_t)(row0 + 8) * NDIM + col) = v1;
        }
    }

    // Last CTA resets scratch state for the next graph replay.
    __syncthreads();
    if (x.tid == 0) {
        __threadfence();
        unsigned int ticket = atomicInc(&g_done, 0xFFFFFFFFu);
        if (ticket == gridDim.x * gridDim.y - 1) {
            g_absmax[0] = 0u;
            g_absmax[1] = 0u;
            g_done = 0u;
            __threadfence();
        }
    }
}

// ============================================================================
// Launch
// ============================================================================
extern "C" void kernel_launch(void* const* d_in, const int* in_sizes, int n_in,
                              void* d_out, int out_size) {
    const float* lhs = (const float*)d_in[0];
    const float* rhs = (const float*)d_in[1];
    float* out = (float*)d_out;

    cudaFuncSetAttribute(qgemm_hmma, cudaFuncAttributeMaxDynamicSharedMemorySize, SMEM_TOTAL);

    const int n4 = (MDIM * KDIM) / 4;
    absmax2_kernel<<<1216, 256>>>((const float4*)lhs, (const float4*)rhs, n4);

    quantAB_kernel<<<QAB_GRID, 256>>>(lhs, rhs);

    dim3 ggrid(NDIM / TILE_N, MDIM / TILE_M);   // (32, 32)
    qgemm_hmma<<<ggrid, 256, SMEM_TOTAL>>>(out);
}